// round 1
// baseline (speedup 1.0000x reference)
#include <cuda_runtime.h>
#include <cuda_bf16.h>
#include <math.h>

// ---------------------------------------------------------------------------
// Problem constants
// ---------------------------------------------------------------------------
#define NN 10000      // nodes
#define NE 80000      // edges
#define NB 64         // graphs
#define NH 4          // heads
#define NC 256        // channels per head
#define ND 256        // model dim
#define HC 1024       // NH*NC

// ---------------------------------------------------------------------------
// Device scratch (static globals: allocation-free rule)
// ---------------------------------------------------------------------------
__device__ float g_x   [NN * ND];
__device__ float g_x2  [NN * ND];
__device__ float g_xsk [NN * ND];
__device__ float g_ea  [NE * ND];
__device__ float g_h1  [NE * 128];
__device__ float g_q   [NN * HC];
__device__ float g_k   [NN * HC];
__device__ float g_v   [NN * HC];
__device__ float g_e   [NE * HC];     // 327 MB
__device__ float g_al  [NE * NH];
__device__ float g_agg [NN * HC];

__device__ int      g_cnt[NN];
__device__ int      g_off[NN + 1];
__device__ int      g_cur[NN];
__device__ int      g_csr[NE];

__device__ float    g_sum [NB * ND];
__device__ unsigned g_mx  [NB * ND];
__device__ int      g_bcnt[NB];
__device__ float    g_en1 [NB * 256];
__device__ float    g_en  [NB * 128];
__device__ float    g_feat[NB * 896];
__device__ float    g_fc1 [NB * 1024];

// ---------------------------------------------------------------------------
// Helpers
// ---------------------------------------------------------------------------
__device__ __forceinline__ unsigned fenc(float x) {
    unsigned u = __float_as_uint(x);
    return (u & 0x80000000u) ? ~u : (u | 0x80000000u);
}
__device__ __forceinline__ float fdec(unsigned u) {
    return (u & 0x80000000u) ? __uint_as_float(u & 0x7FFFFFFFu)
                             : __uint_as_float(~u);
}

__global__ void fill_u32(unsigned* __restrict__ p, unsigned v, int n) {
    int i = blockIdx.x * blockDim.x + threadIdx.x;
    if (i < n) p[i] = v;
}
__global__ void copy_i32(int* __restrict__ dst, const int* __restrict__ src, int n) {
    int i = blockIdx.x * blockDim.x + threadIdx.x;
    if (i < n) dst[i] = src[i];
}

// ---------------------------------------------------------------------------
// SGEMM: C = act(A[MxK] @ B[KxN] + bias),  row-major, bounds-checked
// 128x128 tile, BK=8, 256 threads, 8x8 per thread
// ---------------------------------------------------------------------------
#define BM 128
#define BN 128
#define BK 8

__global__ __launch_bounds__(256)
void sgemm(const float* __restrict__ A, const float* __restrict__ Bm,
           const float* __restrict__ bias, float* __restrict__ Cm,
           int M, int K, int Nc, int act)
{
    __shared__ float As[BK][BM];
    __shared__ float Bs[BK][BN];

    int tid = threadIdx.x;
    int m0 = blockIdx.y * BM;
    int n0 = blockIdx.x * BN;

    int arow = tid >> 1;           // 0..127
    int acol = (tid & 1) * 4;      // 0 or 4
    int brow = tid >> 5;           // 0..7
    int bcol = (tid & 31) * 4;     // 0..124

    int mi = (tid >> 4) * 8;       // 0..120
    int ni = (tid & 15) * 8;       // 0..120

    float acc[8][8];
#pragma unroll
    for (int i = 0; i < 8; i++)
#pragma unroll
        for (int j = 0; j < 8; j++) acc[i][j] = 0.f;

    for (int kt = 0; kt < K; kt += BK) {
#pragma unroll
        for (int j = 0; j < 4; j++) {
            int gm = m0 + arow, gk = kt + acol + j;
            As[acol + j][arow] = (gm < M && gk < K) ? A[(size_t)gm * K + gk] : 0.f;
        }
#pragma unroll
        for (int j = 0; j < 4; j++) {
            int gk = kt + brow, gn = n0 + bcol + j;
            Bs[brow][bcol + j] = (gk < K && gn < Nc) ? Bm[(size_t)gk * Nc + gn] : 0.f;
        }
        __syncthreads();
#pragma unroll
        for (int k = 0; k < BK; k++) {
            float a[8], b[8];
            float4 a0 = *(const float4*)&As[k][mi];
            float4 a1 = *(const float4*)&As[k][mi + 4];
            float4 b0 = *(const float4*)&Bs[k][ni];
            float4 b1 = *(const float4*)&Bs[k][ni + 4];
            a[0]=a0.x; a[1]=a0.y; a[2]=a0.z; a[3]=a0.w;
            a[4]=a1.x; a[5]=a1.y; a[6]=a1.z; a[7]=a1.w;
            b[0]=b0.x; b[1]=b0.y; b[2]=b0.z; b[3]=b0.w;
            b[4]=b1.x; b[5]=b1.y; b[6]=b1.z; b[7]=b1.w;
#pragma unroll
            for (int i = 0; i < 8; i++)
#pragma unroll
                for (int j = 0; j < 8; j++)
                    acc[i][j] += a[i] * b[j];
        }
        __syncthreads();
    }

#pragma unroll
    for (int i = 0; i < 8; i++) {
        int gm = m0 + mi + i;
        if (gm >= M) continue;
#pragma unroll
        for (int j = 0; j < 8; j++) {
            int gn = n0 + ni + j;
            if (gn >= Nc) continue;
            float v = acc[i][j] + (bias ? bias[gn] : 0.f);
            if (act) v = (v > 0.f) ? v : 0.01f * v;
            Cm[(size_t)gm * Nc + gn] = v;
        }
    }
}

// ---------------------------------------------------------------------------
// Node embedding gather
// ---------------------------------------------------------------------------
__global__ void embed_k(const int* __restrict__ ids,
                        const float* __restrict__ emb,
                        float* __restrict__ x)
{
    int idx = blockIdx.x * blockDim.x + threadIdx.x;
    if (idx >= NN * ND) return;
    int n = idx >> 8, c = idx & 255;
    x[idx] = emb[ids[n] * ND + c];
}

// ---------------------------------------------------------------------------
// CSR-by-target build
// ---------------------------------------------------------------------------
__global__ void csr_count_k(const int* __restrict__ ei, int* __restrict__ cnt) {
    int e = blockIdx.x * blockDim.x + threadIdx.x;
    if (e < NE) atomicAdd(&cnt[ei[NE + e]], 1);
}

__global__ __launch_bounds__(1024)
void scan_k(const int* __restrict__ cnt, int* __restrict__ off, int n) {
    __shared__ int sums[1024];
    int per = (n + 1023) / 1024;
    int start = threadIdx.x * per;
    int local = 0;
    for (int i = 0; i < per; i++) {
        int idx = start + i;
        if (idx < n) local += cnt[idx];
    }
    sums[threadIdx.x] = local;
    __syncthreads();
    for (int d = 1; d < 1024; d <<= 1) {
        int v = (threadIdx.x >= (unsigned)d) ? sums[threadIdx.x - d] : 0;
        __syncthreads();
        sums[threadIdx.x] += v;
        __syncthreads();
    }
    int base = (threadIdx.x == 0) ? 0 : sums[threadIdx.x - 1];
    int run = base;
    for (int i = 0; i < per; i++) {
        int idx = start + i;
        if (idx < n) { off[idx] = run; run += cnt[idx]; }
    }
    if (threadIdx.x == 1023) off[n] = sums[1023];
}

__global__ void csr_fill_k(const int* __restrict__ ei, int* __restrict__ cur,
                           int* __restrict__ csr) {
    int e = blockIdx.x * blockDim.x + threadIdx.x;
    if (e < NE) {
        int t = ei[NE + e];
        int p = atomicAdd(&cur[t], 1);
        csr[p] = e;
    }
}

// ---------------------------------------------------------------------------
// alpha[e,h] = (1/16) * sum_c q[tgt,h,c] * (k[src,h,c] + e[e,h,c])
// one warp per (edge, head)
// ---------------------------------------------------------------------------
__global__ void alpha_k(const int* __restrict__ ei,
                        const float* __restrict__ q,
                        const float* __restrict__ k,
                        const float* __restrict__ eb,
                        float* __restrict__ al)
{
    int wid = (blockIdx.x * blockDim.x + threadIdx.x) >> 5;
    int lane = threadIdx.x & 31;
    if (wid >= NE * NH) return;
    int eid = wid >> 2, h = wid & 3;
    int src = ei[eid], tgt = ei[NE + eid];
    const float* qr = q + (size_t)tgt * HC + h * NC;
    const float* kr = k + (size_t)src * HC + h * NC;
    const float* er = eb + (size_t)eid * HC + h * NC;
    float s = 0.f;
#pragma unroll
    for (int c = lane; c < NC; c += 32)
        s += qr[c] * (kr[c] + er[c]);
#pragma unroll
    for (int o = 16; o; o >>= 1) s += __shfl_xor_sync(0xffffffffu, s, o);
    if (lane == 0) al[eid * NH + h] = s * 0.0625f;  // 1/sqrt(256)
}

// ---------------------------------------------------------------------------
// Segment softmax: one warp per (node, head); alpha -> a in place
// ---------------------------------------------------------------------------
__global__ void softmax_k(const int* __restrict__ off,
                          const int* __restrict__ csr,
                          float* __restrict__ al)
{
    int wid = (blockIdx.x * blockDim.x + threadIdx.x) >> 5;
    int lane = threadIdx.x & 31;
    if (wid >= NN * NH) return;
    int n = wid >> 2, h = wid & 3;
    int s0 = off[n], s1 = off[n + 1];
    if (s0 == s1) return;
    float m = -INFINITY;
    for (int i = s0 + lane; i < s1; i += 32)
        m = fmaxf(m, al[csr[i] * NH + h]);
#pragma unroll
    for (int o = 16; o; o >>= 1) m = fmaxf(m, __shfl_xor_sync(0xffffffffu, m, o));
    float sum = 0.f;
    for (int i = s0 + lane; i < s1; i += 32) {
        int idx = csr[i] * NH + h;
        float ex = expf(al[idx] - m);
        al[idx] = ex;
        sum += ex;
    }
#pragma unroll
    for (int o = 16; o; o >>= 1) sum += __shfl_xor_sync(0xffffffffu, sum, o);
    float inv = 1.f / (sum + 1e-16f);
    for (int i = s0 + lane; i < s1; i += 32)
        al[csr[i] * NH + h] *= inv;
}

// ---------------------------------------------------------------------------
// agg[n,h,c] = sum_{edges->n} a[e,h] * (v[src,h,c] + e[e,h,c])
// one 256-thread block per (node, head)
// ---------------------------------------------------------------------------
__global__ __launch_bounds__(256)
void agg_k(const int* __restrict__ ei, const int* __restrict__ off,
           const int* __restrict__ csr, const float* __restrict__ al,
           const float* __restrict__ v, const float* __restrict__ eb,
           float* __restrict__ agg)
{
    int n = blockIdx.x >> 2, h = blockIdx.x & 3, c = threadIdx.x;
    int s0 = off[n], s1 = off[n + 1];
    float acc = 0.f;
    for (int i = s0; i < s1; i++) {
        int eid = csr[i];
        int src = ei[eid];
        float a = al[eid * NH + h];
        acc += a * (v[(size_t)src * HC + h * NC + c] +
                    eb[(size_t)eid * HC + h * NC + c]);
    }
    agg[(size_t)n * HC + h * NC + c] = acc;
}

// x_out = mean_h(agg) + xskip
__global__ void combine_k(const float* __restrict__ agg,
                          const float* __restrict__ xsk,
                          float* __restrict__ xo)
{
    int idx = blockIdx.x * blockDim.x + threadIdx.x;
    if (idx >= NN * ND) return;
    int n = idx >> 8, c = idx & 255;
    const float* ar = agg + (size_t)n * HC;
    float s = ar[c] + ar[256 + c] + ar[512 + c] + ar[768 + c];
    xo[idx] = 0.25f * s + xsk[idx];
}

// ---------------------------------------------------------------------------
// Graph pooling (sum / max / count) with atomics
// ---------------------------------------------------------------------------
__global__ __launch_bounds__(256)
void pool_k(const int* __restrict__ batch, const float* __restrict__ x,
            float* __restrict__ sum, unsigned* __restrict__ mx,
            int* __restrict__ bcnt)
{
    int n = blockIdx.x, c = threadIdx.x;
    int b = batch[n];
    float v = x[(size_t)n * ND + c];
    atomicAdd(&sum[b * ND + c], v);
    atomicMax(&mx[b * ND + c], fenc(v));
    if (c == 0) atomicAdd(&bcnt[b], 1);
}

__global__ __launch_bounds__(256)
void feat_k(const float* __restrict__ sum, const unsigned* __restrict__ mx,
            const int* __restrict__ bcnt, const float* __restrict__ en,
            float* __restrict__ feat)
{
    int b = blockIdx.x, c = threadIdx.x;
    float cnt = (float)bcnt[b];
    float s = sum[b * ND + c];
    feat[b * 896 + c]        = s / cnt;
    feat[b * 896 + 256 + c]  = fdec(mx[b * ND + c]);
    feat[b * 896 + 512 + c]  = s;
    if (c < 128) feat[b * 896 + 768 + c] = en[b * 128 + c];
}

// ---------------------------------------------------------------------------
// Host orchestration
// ---------------------------------------------------------------------------
static inline void run_gemm(const float* A, const float* B, const float* bias,
                            float* C, int M, int K, int Nc, int act)
{
    dim3 grid((Nc + BN - 1) / BN, (M + BM - 1) / BM);
    sgemm<<<grid, 256>>>(A, B, bias, C, M, K, Nc, act);
}

extern "C" void kernel_launch(void* const* d_in, const int* in_sizes, int n_in,
                              void* d_out, int out_size)
{
    const int*   x_ids   = (const int*)  d_in[0];
    const int*   ei      = (const int*)  d_in[1];
    const int*   batch   = (const int*)  d_in[2];
    const float* eattr   = (const float*)d_in[3];
    const float* energies= (const float*)d_in[4];
    const float* nemb    = (const float*)d_in[5];
    const float* ew1     = (const float*)d_in[6];
    const float* eb1     = (const float*)d_in[7];
    const float* ew2     = (const float*)d_in[8];
    const float* eb2     = (const float*)d_in[9];
    const float* wq      = (const float*)d_in[10];
    const float* wk      = (const float*)d_in[11];
    const float* wv      = (const float*)d_in[12];
    const float* we      = (const float*)d_in[13];
    const float* wsk     = (const float*)d_in[14];
    const float* fce_w1  = (const float*)d_in[15];
    const float* fce_b1  = (const float*)d_in[16];
    const float* fce_w2  = (const float*)d_in[17];
    const float* fce_b2  = (const float*)d_in[18];
    const float* fc_w1   = (const float*)d_in[19];
    const float* fc_b1   = (const float*)d_in[20];
    const float* fc_w2   = (const float*)d_in[21];
    const float* fc_b2   = (const float*)d_in[22];
    float* out = (float*)d_out;
    (void)in_sizes; (void)n_in; (void)out_size;

    float *px, *px2, *pxsk, *pea, *ph1, *pq, *pk, *pv, *pe, *pal, *pagg;
    float *psum, *pen1, *pen, *pfeat, *pfc1;
    int *pcnt, *poff, *pcur, *pcsr, *pbcnt;
    unsigned* pmx;
    cudaGetSymbolAddress((void**)&px,   g_x);
    cudaGetSymbolAddress((void**)&px2,  g_x2);
    cudaGetSymbolAddress((void**)&pxsk, g_xsk);
    cudaGetSymbolAddress((void**)&pea,  g_ea);
    cudaGetSymbolAddress((void**)&ph1,  g_h1);
    cudaGetSymbolAddress((void**)&pq,   g_q);
    cudaGetSymbolAddress((void**)&pk,   g_k);
    cudaGetSymbolAddress((void**)&pv,   g_v);
    cudaGetSymbolAddress((void**)&pe,   g_e);
    cudaGetSymbolAddress((void**)&pal,  g_al);
    cudaGetSymbolAddress((void**)&pagg, g_agg);
    cudaGetSymbolAddress((void**)&pcnt, g_cnt);
    cudaGetSymbolAddress((void**)&poff, g_off);
    cudaGetSymbolAddress((void**)&pcur, g_cur);
    cudaGetSymbolAddress((void**)&pcsr, g_csr);
    cudaGetSymbolAddress((void**)&psum, g_sum);
    cudaGetSymbolAddress((void**)&pmx,  g_mx);
    cudaGetSymbolAddress((void**)&pbcnt,g_bcnt);
    cudaGetSymbolAddress((void**)&pen1, g_en1);
    cudaGetSymbolAddress((void**)&pen,  g_en);
    cudaGetSymbolAddress((void**)&pfeat,g_feat);
    cudaGetSymbolAddress((void**)&pfc1, g_fc1);

    // --- node embedding + edge MLP ---
    embed_k<<<(NN * ND + 255) / 256, 256>>>(x_ids, nemb, px);
    run_gemm(eattr, ew1, eb1, ph1, NE, 14, 128, 1);   // lrelu
    run_gemm(ph1, ew2, eb2, pea, NE, 128, ND, 0);

    // --- CSR by target ---
    fill_u32<<<(NN + 255) / 256, 256>>>((unsigned*)pcnt, 0u, NN);
    csr_count_k<<<(NE + 255) / 256, 256>>>(ei, pcnt);
    scan_k<<<1, 1024>>>(pcnt, poff, NN);
    copy_i32<<<(NN + 255) / 256, 256>>>(pcur, poff, NN);
    csr_fill_k<<<(NE + 255) / 256, 256>>>(ei, pcur, pcsr);

    // --- 3 transformer layers ---
    float* xin = px;
    float* xout = px2;
    for (int l = 0; l < 3; l++) {
        const float* wql = wq  + (size_t)l * ND * HC;
        const float* wkl = wk  + (size_t)l * ND * HC;
        const float* wvl = wv  + (size_t)l * ND * HC;
        const float* wel = we  + (size_t)l * ND * HC;
        const float* wsl = wsk + (size_t)l * ND * ND;

        run_gemm(xin, wql, nullptr, pq, NN, ND, HC, 0);
        run_gemm(xin, wkl, nullptr, pk, NN, ND, HC, 0);
        run_gemm(xin, wvl, nullptr, pv, NN, ND, HC, 0);
        run_gemm(pea, wel, nullptr, pe, NE, ND, HC, 0);
        run_gemm(xin, wsl, nullptr, pxsk, NN, ND, ND, 0);

        alpha_k<<<(NE * NH + 7) / 8, 256>>>(ei, pq, pk, pe, pal);
        softmax_k<<<(NN * NH + 7) / 8, 256>>>(poff, pcsr, pal);
        agg_k<<<NN * NH, 256>>>(ei, poff, pcsr, pal, pv, pe, pagg);
        combine_k<<<(NN * ND + 255) / 256, 256>>>(pagg, pxsk, xout);

        float* t = xin; xin = xout; xout = t;
    }
    // after 3 layers, result lives in xin

    // --- pooling ---
    fill_u32<<<(NB * ND + 255) / 256, 256>>>((unsigned*)psum, 0u, NB * ND);
    fill_u32<<<(NB * ND + 255) / 256, 256>>>(pmx, 0u, NB * ND);
    fill_u32<<<(NB + 255) / 256, 256>>>((unsigned*)pbcnt, 0u, NB);
    pool_k<<<NN, 256>>>(batch, xin, psum, pmx, pbcnt);

    // --- energy MLP ---
    run_gemm(energies, fce_w1, fce_b1, pen1, NB, 201, 256, 1);  // lrelu
    run_gemm(pen1, fce_w2, fce_b2, pen, NB, 256, 128, 0);

    // --- feature concat + head ---
    feat_k<<<NB, 256>>>(psum, pmx, pbcnt, pen, pfeat);
    run_gemm(pfeat, fc_w1, fc_b1, pfc1, NB, 896, 1024, 1);      // lrelu
    run_gemm(pfc1, fc_w2, fc_b2, out, NB, 1024, 804, 0);
}

// round 6
// speedup vs baseline: 1.8055x; 1.8055x over previous
#include <cuda_runtime.h>
#include <cuda_bf16.h>
#include <math.h>

// ---------------------------------------------------------------------------
// Problem constants
// ---------------------------------------------------------------------------
#define NN 10000      // nodes
#define NE 80000      // edges
#define NB 64         // graphs
#define NH 4          // heads
#define NC 256        // channels per head
#define ND 256        // model dim
#define HC 1024       // NH*NC
#define PS 4352       // proj row stride: q(1024)|k(1024)|v(1024)|qe(1024)|skip(256)

// ---------------------------------------------------------------------------
// Device scratch (static globals: allocation-free rule)
// ---------------------------------------------------------------------------
__device__ float g_x    [NN * ND];
__device__ float g_x2   [NN * ND];
__device__ float g_proj [NN * PS];     // 174 MB: per-node q,k,v,qe,skip
__device__ float g_ea   [NE * ND];
__device__ float g_h1   [NE * 128];
__device__ float g_al   [NE * NH];
__device__ float g_aggea[NN * HC];     // attention-weighted raw edge features
__device__ float g_wcat [3 * ND * PS]; // concat weights per layer
__device__ float g_wes  [3 * HC * ND]; // We_stack[l][h*256+d][c] = we[l][d][h*256+c]

__device__ int      g_cnt[NN];
__device__ int      g_off[NN + 1];
__device__ int      g_cur[NN];
__device__ int      g_csr[NE];

__device__ float    g_sum [NB * ND];
__device__ unsigned g_mx  [NB * ND];
__device__ int      g_bcnt[NB];
__device__ float    g_en1 [NB * 256];
__device__ float    g_en  [NB * 128];
__device__ float    g_feat[NB * 896];
__device__ float    g_fc1 [NB * 1024];

// ---------------------------------------------------------------------------
// Helpers
// ---------------------------------------------------------------------------
__device__ __forceinline__ unsigned fenc(float x) {
    unsigned u = __float_as_uint(x);
    return (u & 0x80000000u) ? ~u : (u | 0x80000000u);
}
__device__ __forceinline__ float fdec(unsigned u) {
    return (u & 0x80000000u) ? __uint_as_float(u & 0x7FFFFFFFu)
                             : __uint_as_float(~u);
}

__global__ void fill_u32(unsigned* __restrict__ p, unsigned v, int n) {
    int i = blockIdx.x * blockDim.x + threadIdx.x;
    if (i < n) p[i] = v;
}
__global__ void copy_i32(int* __restrict__ dst, const int* __restrict__ src, int n) {
    int i = blockIdx.x * blockDim.x + threadIdx.x;
    if (i < n) dst[i] = src[i];
}

// ---------------------------------------------------------------------------
// SGEMM: 128x128 tile, BK=8, 256 threads, 8x8 per thread. Row-major,
// contiguous (lda=K, ldb=N, ldc=N).  mode: 0=store, 1=lrelu store,
// 2 = C += 0.25 * acc (no bias/act).
// Double-buffered smem, ONE __syncthreads per K-step:
//   at each barrier, all warps finished computing buf and writing buf^1;
//   next iter reads buf^1 (visible) and overwrites buf (no readers left).
// ---------------------------------------------------------------------------
#define BM 128
#define BN 128
#define BK 8

__global__ __launch_bounds__(256)
void sgemm(const float* __restrict__ A, const float* __restrict__ Bm,
           const float* __restrict__ bias, float* __restrict__ Cm,
           int M, int K, int Nc, int mode)
{
    __shared__ float As[2][BK][BM];
    __shared__ float Bs[2][BK][BN];

    int tid = threadIdx.x;
    int m0 = blockIdx.y * BM;
    int n0 = blockIdx.x * BN;

    int arow = tid >> 1;           // 0..127
    int acol = (tid & 1) * 4;      // 0 or 4
    int brow = tid >> 5;           // 0..7
    int bcol = (tid & 31) * 4;     // 0..124

    int mi = (tid >> 4) * 8;       // 0..120
    int ni = (tid & 15) * 8;       // 0..120

    int gmA = m0 + arow;           // fixed A row for this thread

    float acc[8][8];
#pragma unroll
    for (int i = 0; i < 8; i++)
#pragma unroll
        for (int j = 0; j < 8; j++) acc[i][j] = 0.f;

    float ra[4], rb[4];

    // prologue: load tile 0 into regs, store to buf 0
#pragma unroll
    for (int j = 0; j < 4; j++) {
        int gk = acol + j;
        ra[j] = (gmA < M && gk < K) ? A[(size_t)gmA * K + gk] : 0.f;
    }
#pragma unroll
    for (int j = 0; j < 4; j++) {
        int gk = brow, gn = n0 + bcol + j;
        rb[j] = (gk < K && gn < Nc) ? Bm[(size_t)gk * Nc + gn] : 0.f;
    }
#pragma unroll
    for (int j = 0; j < 4; j++) As[0][acol + j][arow] = ra[j];
#pragma unroll
    for (int j = 0; j < 4; j++) Bs[0][brow][bcol + j] = rb[j];
    __syncthreads();

    int buf = 0;
    for (int kt = 0; kt < K; kt += BK) {
        int next = kt + BK;
        bool more = next < K;
        // prefetch next tile into registers (overlaps with compute below)
        if (more) {
#pragma unroll
            for (int j = 0; j < 4; j++) {
                int gk = next + acol + j;
                ra[j] = (gmA < M && gk < K) ? A[(size_t)gmA * K + gk] : 0.f;
            }
#pragma unroll
            for (int j = 0; j < 4; j++) {
                int gk = next + brow, gn = n0 + bcol + j;
                rb[j] = (gk < K && gn < Nc) ? Bm[(size_t)gk * Nc + gn] : 0.f;
            }
        }
        // compute on current buffer
#pragma unroll
        for (int k = 0; k < BK; k++) {
            float a[8], b[8];
            float4 a0 = *(const float4*)&As[buf][k][mi];
            float4 a1 = *(const float4*)&As[buf][k][mi + 4];
            float4 b0 = *(const float4*)&Bs[buf][k][ni];
            float4 b1 = *(const float4*)&Bs[buf][k][ni + 4];
            a[0]=a0.x; a[1]=a0.y; a[2]=a0.z; a[3]=a0.w;
            a[4]=a1.x; a[5]=a1.y; a[6]=a1.z; a[7]=a1.w;
            b[0]=b0.x; b[1]=b0.y; b[2]=b0.z; b[3]=b0.w;
            b[4]=b1.x; b[5]=b1.y; b[6]=b1.z; b[7]=b1.w;
#pragma unroll
            for (int i = 0; i < 8; i++)
#pragma unroll
                for (int j = 0; j < 8; j++)
                    acc[i][j] += a[i] * b[j];
        }
        if (more) {
            // store prefetched tile into the other buffer, then one barrier
#pragma unroll
            for (int j = 0; j < 4; j++) As[buf ^ 1][acol + j][arow] = ra[j];
#pragma unroll
            for (int j = 0; j < 4; j++) Bs[buf ^ 1][brow][bcol + j] = rb[j];
            __syncthreads();
            buf ^= 1;
        }
    }

#pragma unroll
    for (int i = 0; i < 8; i++) {
        int gm = m0 + mi + i;
        if (gm >= M) continue;
#pragma unroll
        for (int j = 0; j < 8; j++) {
            int gn = n0 + ni + j;
            if (gn >= Nc) continue;
            size_t idx = (size_t)gm * Nc + gn;
            if (mode == 2) {
                Cm[idx] += 0.25f * acc[i][j];
            } else {
                float v = acc[i][j] + (bias ? bias[gn] : 0.f);
                if (mode == 1) v = (v > 0.f) ? v : 0.01f * v;
                Cm[idx] = v;
            }
        }
    }
}

// ---------------------------------------------------------------------------
// Weight concat: wcat[l][i][0:1024]=wq, [1024:2048]=wk, [2048:3072]=wv,
// [4096:4352]=wskip.  (columns 3072:4096 = wqe, filled by wqe_k)
// ---------------------------------------------------------------------------
__global__ void wcat_k(const float* __restrict__ wq, const float* __restrict__ wk,
                       const float* __restrict__ wv, const float* __restrict__ wsk,
                       float* __restrict__ wcat)
{
    int idx = blockIdx.x * blockDim.x + threadIdx.x;
    int total = 3 * ND * PS;
    if (idx >= total) return;
    int l = idx / (ND * PS);
    int r = (idx / PS) % ND;
    int c = idx % PS;
    float v;
    if (c < 1024)       v = wq [(size_t)l * ND * HC + (size_t)r * HC + c];
    else if (c < 2048)  v = wk [(size_t)l * ND * HC + (size_t)r * HC + (c - 1024)];
    else if (c < 3072)  v = wv [(size_t)l * ND * HC + (size_t)r * HC + (c - 2048)];
    else if (c < 4096)  return;  // wqe slot, filled separately
    else                v = wsk[(size_t)l * ND * ND + (size_t)r * ND + (c - 4096)];
    wcat[idx] = v;
}

// ---------------------------------------------------------------------------
// Wqe precompute: per (l,h): Wqe_lh[i][d] = sum_c wq[l][i,hC+c] * we[l][d,hC+c]
// Written into wcat columns 3072 + h*256 + d (ldc = PS). grid (2,2,12).
// (small: 0.4 GF total — simple single-buffer loop is fine)
// ---------------------------------------------------------------------------
__global__ __launch_bounds__(256)
void wqe_k(const float* __restrict__ wq, const float* __restrict__ we,
           float* __restrict__ wcat)
{
    __shared__ float As[BK][BM];
    __shared__ float Bs[BK][BN];

    int z = blockIdx.z;
    int l = z >> 2, h = z & 3;
    const float* A = wq + (size_t)l * ND * HC + h * NC;   // [i][c], lda=HC
    const float* B = we + (size_t)l * ND * HC + h * NC;   // [d][c], ldb=HC
    float* C = wcat + (size_t)l * ND * PS + 3072 + h * NC; // [i][d], ldc=PS

    int tid = threadIdx.x;
    int m0 = blockIdx.y * BM;
    int n0 = blockIdx.x * BN;

    int arow = tid >> 1;
    int acol = (tid & 1) * 4;
    int mi = (tid >> 4) * 8;
    int ni = (tid & 15) * 8;

    float acc[8][8];
#pragma unroll
    for (int i = 0; i < 8; i++)
#pragma unroll
        for (int j = 0; j < 8; j++) acc[i][j] = 0.f;

    for (int kt = 0; kt < ND; kt += BK) {
#pragma unroll
        for (int j = 0; j < 4; j++)
            As[acol + j][arow] = A[(size_t)(m0 + arow) * HC + kt + acol + j];
        // B transposed: Bs[k][n] = B[n*HC + k]
#pragma unroll
        for (int j = 0; j < 4; j++)
            Bs[acol + j][arow] = B[(size_t)(n0 + arow) * HC + kt + acol + j];
        __syncthreads();
#pragma unroll
        for (int k = 0; k < BK; k++) {
            float a[8], b[8];
            float4 a0 = *(const float4*)&As[k][mi];
            float4 a1 = *(const float4*)&As[k][mi + 4];
            float4 b0 = *(const float4*)&Bs[k][ni];
            float4 b1 = *(const float4*)&Bs[k][ni + 4];
            a[0]=a0.x; a[1]=a0.y; a[2]=a0.z; a[3]=a0.w;
            a[4]=a1.x; a[5]=a1.y; a[6]=a1.z; a[7]=a1.w;
            b[0]=b0.x; b[1]=b0.y; b[2]=b0.z; b[3]=b0.w;
            b[4]=b1.x; b[5]=b1.y; b[6]=b1.z; b[7]=b1.w;
#pragma unroll
            for (int i = 0; i < 8; i++)
#pragma unroll
                for (int j = 0; j < 8; j++)
                    acc[i][j] += a[i] * b[j];
        }
        __syncthreads();
    }
#pragma unroll
    for (int i = 0; i < 8; i++)
#pragma unroll
        for (int j = 0; j < 8; j++)
            C[(size_t)(m0 + mi + i) * PS + n0 + ni + j] = acc[i][j];
}

// We_stack[l][h*256+d][c] = we[l][d][h*256+c]
__global__ void westack_k(const float* __restrict__ we, float* __restrict__ wes) {
    int idx = blockIdx.x * blockDim.x + threadIdx.x;
    if (idx >= 3 * HC * ND) return;
    int l = idx / (HC * ND);
    int r = (idx / ND) % HC;
    int c = idx % ND;
    int h = r >> 8, d = r & 255;
    wes[idx] = we[(size_t)l * ND * HC + (size_t)d * HC + h * NC + c];
}

// ---------------------------------------------------------------------------
// Node embedding gather
// ---------------------------------------------------------------------------
__global__ void embed_k(const int* __restrict__ ids,
                        const float* __restrict__ emb,
                        float* __restrict__ x)
{
    int idx = blockIdx.x * blockDim.x + threadIdx.x;
    if (idx >= NN * ND) return;
    int n = idx >> 8, c = idx & 255;
    x[idx] = emb[ids[n] * ND + c];
}

// ---------------------------------------------------------------------------
// CSR-by-target build
// ---------------------------------------------------------------------------
__global__ void csr_count_k(const int* __restrict__ ei, int* __restrict__ cnt) {
    int e = blockIdx.x * blockDim.x + threadIdx.x;
    if (e < NE) atomicAdd(&cnt[ei[NE + e]], 1);
}

__global__ __launch_bounds__(1024)
void scan_k(const int* __restrict__ cnt, int* __restrict__ off, int n) {
    __shared__ int sums[1024];
    int per = (n + 1023) / 1024;
    int start = threadIdx.x * per;
    int local = 0;
    for (int i = 0; i < per; i++) {
        int idx = start + i;
        if (idx < n) local += cnt[idx];
    }
    sums[threadIdx.x] = local;
    __syncthreads();
    for (int d = 1; d < 1024; d <<= 1) {
        int v = (threadIdx.x >= (unsigned)d) ? sums[threadIdx.x - d] : 0;
        __syncthreads();
        sums[threadIdx.x] += v;
        __syncthreads();
    }
    int base = (threadIdx.x == 0) ? 0 : sums[threadIdx.x - 1];
    int run = base;
    for (int i = 0; i < per; i++) {
        int idx = start + i;
        if (idx < n) { off[idx] = run; run += cnt[idx]; }
    }
    if (threadIdx.x == 1023) off[n] = sums[1023];
}

__global__ void csr_fill_k(const int* __restrict__ ei, int* __restrict__ cur,
                           int* __restrict__ csr) {
    int e = blockIdx.x * blockDim.x + threadIdx.x;
    if (e < NE) {
        int t = ei[NE + e];
        int p = atomicAdd(&cur[t], 1);
        csr[p] = e;
    }
}

// ---------------------------------------------------------------------------
// alpha[e,h] = (1/16)*( q[tgt,h]·k[src,h] + ea[e]·qe[tgt,h] )
// one warp per edge, all 4 heads.  q/k/qe live in proj (stride PS).
// ---------------------------------------------------------------------------
__global__ __launch_bounds__(256)
void alpha_k(const int* __restrict__ ei,
             const float* __restrict__ proj,
             const float* __restrict__ ea,
             float* __restrict__ al)
{
    int wid = (blockIdx.x * blockDim.x + threadIdx.x) >> 5;
    int lane = threadIdx.x & 31;
    if (wid >= NE) return;
    int e = wid;
    int src = ei[e], tgt = ei[NE + e];
    const float* qr  = proj + (size_t)tgt * PS;          // q
    const float* kr  = proj + (size_t)src * PS + 1024;   // k
    const float* qer = proj + (size_t)tgt * PS + 3072;   // qe
    const float* ear = ea + (size_t)e * ND;
    float acc[4] = {0.f, 0.f, 0.f, 0.f};
    for (int c = lane; c < NC; c += 32) {
        float eav = ear[c];
#pragma unroll
        for (int h = 0; h < 4; h++)
            acc[h] += qr[h * NC + c] * kr[h * NC + c] + qer[h * NC + c] * eav;
    }
#pragma unroll
    for (int o = 16; o; o >>= 1)
#pragma unroll
        for (int h = 0; h < 4; h++)
            acc[h] += __shfl_xor_sync(0xffffffffu, acc[h], o);
    if (lane == 0) {
#pragma unroll
        for (int h = 0; h < 4; h++)
            al[e * NH + h] = acc[h] * 0.0625f;  // 1/sqrt(256)
    }
}

// ---------------------------------------------------------------------------
// Segment softmax: one warp per (node, head); alpha -> a in place
// ---------------------------------------------------------------------------
__global__ void softmax_k(const int* __restrict__ off,
                          const int* __restrict__ csr,
                          float* __restrict__ al)
{
    int wid = (blockIdx.x * blockDim.x + threadIdx.x) >> 5;
    int lane = threadIdx.x & 31;
    if (wid >= NN * NH) return;
    int n = wid >> 2, h = wid & 3;
    int s0 = off[n], s1 = off[n + 1];
    if (s0 == s1) return;
    float m = -INFINITY;
    for (int i = s0 + lane; i < s1; i += 32)
        m = fmaxf(m, al[csr[i] * NH + h]);
#pragma unroll
    for (int o = 16; o; o >>= 1) m = fmaxf(m, __shfl_xor_sync(0xffffffffu, m, o));
    float sum = 0.f;
    for (int i = s0 + lane; i < s1; i += 32) {
        int idx = csr[i] * NH + h;
        float ex = expf(al[idx] - m);
        al[idx] = ex;
        sum += ex;
    }
#pragma unroll
    for (int o = 16; o; o >>= 1) sum += __shfl_xor_sync(0xffffffffu, sum, o);
    float inv = 1.f / (sum + 1e-16f);
    for (int i = s0 + lane; i < s1; i += 32)
        al[csr[i] * NH + h] *= inv;
}

// ---------------------------------------------------------------------------
// Aggregation (one block per node, 256 threads = channel c):
//   xout[n,c]        = 0.25 * sum_h sum_e a[e,h]*v[src,h,c] + skip[n,c]
//   aggea[n,h*256+c] = sum_e a[e,h]*ea[e,c]
// (edge-feature part of the message added later via GEMM: += 0.25*aggea@wes)
// ---------------------------------------------------------------------------
__global__ __launch_bounds__(256)
void agg_k(const int* __restrict__ ei, const int* __restrict__ off,
           const int* __restrict__ csr, const float* __restrict__ al,
           const float* __restrict__ proj, const float* __restrict__ ea,
           float* __restrict__ aggea, float* __restrict__ xout)
{
    int n = blockIdx.x, c = threadIdx.x;
    int s0 = off[n], s1 = off[n + 1];
    float sv = 0.f;
    float ae[4] = {0.f, 0.f, 0.f, 0.f};
    for (int i = s0; i < s1; i++) {
        int e = csr[i];
        int src = ei[e];
        float a0 = al[e * NH + 0];
        float a1 = al[e * NH + 1];
        float a2 = al[e * NH + 2];
        float a3 = al[e * NH + 3];
        const float* vr = proj + (size_t)src * PS + 2048;
        sv += a0 * vr[c] + a1 * vr[NC + c] + a2 * vr[2 * NC + c] + a3 * vr[3 * NC + c];
        float eav = ea[(size_t)e * ND + c];
        ae[0] += a0 * eav; ae[1] += a1 * eav; ae[2] += a2 * eav; ae[3] += a3 * eav;
    }
    xout[(size_t)n * ND + c] = 0.25f * sv + proj[(size_t)n * PS + 4096 + c];
    float* ar = aggea + (size_t)n * HC;
    ar[c] = ae[0]; ar[NC + c] = ae[1]; ar[2 * NC + c] = ae[2]; ar[3 * NC + c] = ae[3];
}

// ---------------------------------------------------------------------------
// Graph pooling (sum / max / count) with atomics
// ---------------------------------------------------------------------------
__global__ __launch_bounds__(256)
void pool_k(const int* __restrict__ batch, const float* __restrict__ x,
            float* __restrict__ sum, unsigned* __restrict__ mx,
            int* __restrict__ bcnt)
{
    int n = blockIdx.x, c = threadIdx.x;
    int b = batch[n];
    float v = x[(size_t)n * ND + c];
    atomicAdd(&sum[b * ND + c], v);
    atomicMax(&mx[b * ND + c], fenc(v));
    if (c == 0) atomicAdd(&bcnt[b], 1);
}

__global__ __launch_bounds__(256)
void feat_k(const float* __restrict__ sum, const unsigned* __restrict__ mx,
            const int* __restrict__ bcnt, const float* __restrict__ en,
            float* __restrict__ feat)
{
    int b = blockIdx.x, c = threadIdx.x;
    float cnt = (float)bcnt[b];
    float s = sum[b * ND + c];
    feat[b * 896 + c]        = s / cnt;
    feat[b * 896 + 256 + c]  = fdec(mx[b * ND + c]);
    feat[b * 896 + 512 + c]  = s;
    if (c < 128) feat[b * 896 + 768 + c] = en[b * 128 + c];
}

// ---------------------------------------------------------------------------
// Host orchestration
// ---------------------------------------------------------------------------
static inline void run_gemm(const float* A, const float* B, const float* bias,
                            float* C, int M, int K, int Nc, int mode)
{
    dim3 grid((Nc + BN - 1) / BN, (M + BM - 1) / BM);
    sgemm<<<grid, 256>>>(A, B, bias, C, M, K, Nc, mode);
}

extern "C" void kernel_launch(void* const* d_in, const int* in_sizes, int n_in,
                              void* d_out, int out_size)
{
    const int*   x_ids   = (const int*)  d_in[0];
    const int*   ei      = (const int*)  d_in[1];
    const int*   batch   = (const int*)  d_in[2];
    const float* eattr   = (const float*)d_in[3];
    const float* energies= (const float*)d_in[4];
    const float* nemb    = (const float*)d_in[5];
    const float* ew1     = (const float*)d_in[6];
    const float* eb1     = (const float*)d_in[7];
    const float* ew2     = (const float*)d_in[8];
    const float* eb2     = (const float*)d_in[9];
    const float* wq      = (const float*)d_in[10];
    const float* wk      = (const float*)d_in[11];
    const float* wv      = (const float*)d_in[12];
    const float* we      = (const float*)d_in[13];
    const float* wsk     = (const float*)d_in[14];
    const float* fce_w1  = (const float*)d_in[15];
    const float* fce_b1  = (const float*)d_in[16];
    const float* fce_w2  = (const float*)d_in[17];
    const float* fce_b2  = (const float*)d_in[18];
    const float* fc_w1   = (const float*)d_in[19];
    const float* fc_b1   = (const float*)d_in[20];
    const float* fc_w2   = (const float*)d_in[21];
    const float* fc_b2   = (const float*)d_in[22];
    float* out = (float*)d_out;
    (void)in_sizes; (void)n_in; (void)out_size;

    float *px, *px2, *pproj, *pea, *ph1, *pal, *paggea, *pwcat, *pwes;
    float *psum, *pen1, *pen, *pfeat, *pfc1;
    int *pcnt, *poff, *pcur, *pcsr, *pbcnt;
    unsigned* pmx;
    cudaGetSymbolAddress((void**)&px,    g_x);
    cudaGetSymbolAddress((void**)&px2,   g_x2);
    cudaGetSymbolAddress((void**)&pproj, g_proj);
    cudaGetSymbolAddress((void**)&pea,   g_ea);
    cudaGetSymbolAddress((void**)&ph1,   g_h1);
    cudaGetSymbolAddress((void**)&pal,   g_al);
    cudaGetSymbolAddress((void**)&paggea,g_aggea);
    cudaGetSymbolAddress((void**)&pwcat, g_wcat);
    cudaGetSymbolAddress((void**)&pwes,  g_wes);
    cudaGetSymbolAddress((void**)&pcnt,  g_cnt);
    cudaGetSymbolAddress((void**)&poff,  g_off);
    cudaGetSymbolAddress((void**)&pcur,  g_cur);
    cudaGetSymbolAddress((void**)&pcsr,  g_csr);
    cudaGetSymbolAddress((void**)&psum,  g_sum);
    cudaGetSymbolAddress((void**)&pmx,   g_mx);
    cudaGetSymbolAddress((void**)&pbcnt, g_bcnt);
    cudaGetSymbolAddress((void**)&pen1,  g_en1);
    cudaGetSymbolAddress((void**)&pen,   g_en);
    cudaGetSymbolAddress((void**)&pfeat, g_feat);
    cudaGetSymbolAddress((void**)&pfc1,  g_fc1);

    // --- prep (slots 1-5), then big projection GEMM at slot 6 for ncu -s5 ---
    embed_k<<<(NN * ND + 255) / 256, 256>>>(x_ids, nemb, px);                 // 1
    wcat_k<<<(3 * ND * PS + 255) / 256, 256>>>(wq, wk, wv, wsk, pwcat);       // 2
    {
        dim3 g(2, 2, 12);
        wqe_k<<<g, 256>>>(wq, we, pwcat);                                     // 3
    }
    westack_k<<<(3 * HC * ND + 255) / 256, 256>>>(we, pwes);                  // 4
    run_gemm(eattr, ew1, eb1, ph1, NE, 14, 128, 1);                           // 5
    run_gemm(px, pwcat, nullptr, pproj, NN, ND, PS, 0);                       // 6 (layer 0 proj)
    run_gemm(ph1, ew2, eb2, pea, NE, 128, ND, 0);                             // 7

    // --- CSR by target ---
    fill_u32<<<(NN + 255) / 256, 256>>>((unsigned*)pcnt, 0u, NN);
    csr_count_k<<<(NE + 255) / 256, 256>>>(ei, pcnt);
    scan_k<<<1, 1024>>>(pcnt, poff, NN);
    copy_i32<<<(NN + 255) / 256, 256>>>(pcur, poff, NN);
    csr_fill_k<<<(NE + 255) / 256, 256>>>(ei, pcur, pcsr);

    // --- 3 transformer layers ---
    float* xin = px;
    float* xout = px2;
    for (int l = 0; l < 3; l++) {
        const float* wcatl = pwcat + (size_t)l * ND * PS;
        const float* wesl  = pwes  + (size_t)l * HC * ND;

        if (l > 0)  // layer 0 projection already issued above
            run_gemm(xin, wcatl, nullptr, pproj, NN, ND, PS, 0);

        alpha_k<<<(NE + 7) / 8, 256>>>(ei, pproj, pea, pal);
        softmax_k<<<(NN * NH + 7) / 8, 256>>>(poff, pcsr, pal);
        agg_k<<<NN, 256>>>(ei, poff, pcsr, pal, pproj, pea, paggea, xout);
        // xout += 0.25 * aggea @ We_stack[l]
        run_gemm(paggea, wesl, nullptr, xout, NN, HC, ND, 2);

        float* t = xin; xin = xout; xout = t;
    }
    // after 3 layers, result lives in xin

    // --- pooling ---
    fill_u32<<<(NB * ND + 255) / 256, 256>>>((unsigned*)psum, 0u, NB * ND);
    fill_u32<<<(NB * ND + 255) / 256, 256>>>(pmx, 0u, NB * ND);
    fill_u32<<<(NB + 255) / 256, 256>>>((unsigned*)pbcnt, 0u, NB);
    pool_k<<<NN, 256>>>(batch, xin, psum, pmx, pbcnt);

    // --- energy MLP ---
    run_gemm(energies, fce_w1, fce_b1, pen1, NB, 201, 256, 1);  // lrelu
    run_gemm(pen1, fce_w2, fce_b2, pen, NB, 256, 128, 0);

    // --- feature concat + head ---
    feat_k<<<NB, 256>>>(psum, pmx, pbcnt, pen, pfeat);
    run_gemm(pfeat, fc_w1, fc_b1, pfc1, NB, 896, 1024, 1);      // lrelu
    run_gemm(pfc1, fc_w2, fc_b2, out, NB, 1024, 804, 0);
}

// round 7
// speedup vs baseline: 2.5521x; 1.4135x over previous
#include <cuda_runtime.h>
#include <cuda_bf16.h>
#include <math.h>
#include <stdint.h>

// ---------------------------------------------------------------------------
// Problem constants
// ---------------------------------------------------------------------------
#define NN 10000      // nodes
#define NE 80000      // edges
#define NB 64         // graphs
#define NH 4          // heads
#define NC 256        // channels per head
#define ND 256        // model dim
#define HC 1024       // NH*NC
#define PS 4352       // proj row stride: q(1024)|k(1024)|v(1024)|qe(1024)|skip(256)

// ---------------------------------------------------------------------------
// Device scratch (static globals: allocation-free rule)
// ---------------------------------------------------------------------------
__device__ float g_x    [NN * ND];
__device__ float g_x2   [NN * ND];
__device__ float g_proj [NN * PS];
__device__ float g_ea   [NE * ND];
__device__ float g_h1   [NE * 128];
__device__ float g_al   [NE * NH];
__device__ float g_aggea[NN * HC];
__device__ float g_wcat [3 * ND * PS];
__device__ float g_wes  [3 * HC * ND];

__device__ int      g_cnt[NN];
__device__ int      g_off[NN + 1];
__device__ int      g_cur[NN];
__device__ int      g_csr[NE];

__device__ float    g_sum [NB * ND];
__device__ unsigned g_mx  [NB * ND];
__device__ int      g_bcnt[NB];
__device__ float    g_en1 [NB * 256];
__device__ float    g_en  [NB * 128];
__device__ float    g_feat[NB * 896];
__device__ float    g_fc1 [NB * 1024];

// ---------------------------------------------------------------------------
// Helpers
// ---------------------------------------------------------------------------
__device__ __forceinline__ unsigned fenc(float x) {
    unsigned u = __float_as_uint(x);
    return (u & 0x80000000u) ? ~u : (u | 0x80000000u);
}
__device__ __forceinline__ float fdec(unsigned u) {
    return (u & 0x80000000u) ? __uint_as_float(u & 0x7FFFFFFFu)
                             : __uint_as_float(~u);
}

__global__ void fill_u32(unsigned* __restrict__ p, unsigned v, int n) {
    int i = blockIdx.x * blockDim.x + threadIdx.x;
    if (i < n) p[i] = v;
}
__global__ void copy_i32(int* __restrict__ dst, const int* __restrict__ src, int n) {
    int i = blockIdx.x * blockDim.x + threadIdx.x;
    if (i < n) dst[i] = src[i];
}

// ---------------------------------------------------------------------------
// 3xTF32 helpers
// ---------------------------------------------------------------------------
__device__ __forceinline__ void split_tf32(float x, uint32_t& hi, uint32_t& lo) {
    uint32_t h;
    asm("cvt.rna.tf32.f32 %0, %1;" : "=r"(h) : "f"(x));
    float l = x - __uint_as_float(h);
    uint32_t lr;
    asm("cvt.rna.tf32.f32 %0, %1;" : "=r"(lr) : "f"(l));
    hi = h; lo = lr;
}

__device__ __forceinline__ void mma_tf32(float* d, const uint32_t* a, const uint32_t* b) {
    asm volatile(
        "mma.sync.aligned.m16n8k8.row.col.f32.tf32.tf32.f32 "
        "{%0,%1,%2,%3}, {%4,%5,%6,%7}, {%8,%9}, {%0,%1,%2,%3};"
        : "+f"(d[0]), "+f"(d[1]), "+f"(d[2]), "+f"(d[3])
        : "r"(a[0]), "r"(a[1]), "r"(a[2]), "r"(a[3]), "r"(b[0]), "r"(b[1]));
}

// ---------------------------------------------------------------------------
// Tensor-core GEMM (3xTF32, fp32-accurate): C = act(A[MxK] @ B[KxN] + bias)
// 128x128x16 CTA tile, 256 threads = 8 warps of 64x32, m16n8k8 mma.
// Double-buffered smem, one __syncthreads per tile iteration.
// mode: 0=store, 1=lrelu store, 2 = C += 0.25 * acc.
// As[m][k] stride 20 (frag banks 20m+k: conflict-free);
// Bs[k][n] stride 136 (frag banks 8k+n: conflict-free).
// ---------------------------------------------------------------------------
#define TBM 128
#define TBN 128
#define TBK 16

__global__ __launch_bounds__(256)
void sgemm(const float* __restrict__ A, const float* __restrict__ Bm,
           const float* __restrict__ bias, float* __restrict__ Cm,
           int M, int K, int Nc, int mode)
{
    __shared__ float As[2][TBM][TBK + 4];   // stride 20
    __shared__ float Bs[2][TBK][TBN + 8];   // stride 136

    int tid  = threadIdx.x;
    int lane = tid & 31;
    int wid  = tid >> 5;
    int wm   = wid >> 2;         // 0..1
    int wn   = wid & 3;          // 0..3
    int lm   = lane >> 2;        // 0..7
    int lk   = lane & 3;         // 0..3

    int m0 = blockIdx.y * TBM;
    int n0 = blockIdx.x * TBN;

    // per-thread gmem load coords (2 float4 each for A and B)
    // A: f = tid + 256p -> row f>>2 (0..127), quad (f&3)*4
    // B: f -> krow f>>5 (0..15), quad (f&31)*4
    float acc[16][4];
#pragma unroll
    for (int i = 0; i < 16; i++)
#pragma unroll
        for (int j = 0; j < 4; j++) acc[i][j] = 0.f;

    float ra[8], rb[8];
    bool vecK = ((K & 3) == 0);

    // ---- load tile kt into registers ----
    auto loadTile = [&](int kt) {
        bool fullA = vecK && (m0 + TBM <= M) && (kt + TBK <= K);
        bool fullB = (kt + TBK <= K) && (n0 + TBN <= Nc);  // Nc always %4==0 here
#pragma unroll
        for (int p = 0; p < 2; p++) {
            int f = tid + p * 256;
            int r = f >> 2, q = (f & 3) * 4;
            int gm = m0 + r;
            if (fullA) {
                float4 v = *(const float4*)&A[(size_t)gm * K + kt + q];
                ra[p*4+0]=v.x; ra[p*4+1]=v.y; ra[p*4+2]=v.z; ra[p*4+3]=v.w;
            } else {
#pragma unroll
                for (int j = 0; j < 4; j++) {
                    int gk = kt + q + j;
                    ra[p*4+j] = (gm < M && gk < K) ? A[(size_t)gm * K + gk] : 0.f;
                }
            }
            int kr = f >> 5, nq = (f & 31) * 4;
            int gk = kt + kr;
            if (fullB) {
                float4 v = *(const float4*)&Bm[(size_t)gk * Nc + n0 + nq];
                rb[p*4+0]=v.x; rb[p*4+1]=v.y; rb[p*4+2]=v.z; rb[p*4+3]=v.w;
            } else {
#pragma unroll
                for (int j = 0; j < 4; j++) {
                    int gn = n0 + nq + j;
                    rb[p*4+j] = (gk < K && gn < Nc) ? Bm[(size_t)gk * Nc + gn] : 0.f;
                }
            }
        }
    };
    auto storeTile = [&](int buf) {
#pragma unroll
        for (int p = 0; p < 2; p++) {
            int f = tid + p * 256;
            int r = f >> 2, q = (f & 3) * 4;
            float4* pa = (float4*)&As[buf][r][q];
            *pa = make_float4(ra[p*4+0], ra[p*4+1], ra[p*4+2], ra[p*4+3]);
            int kr = f >> 5, nq = (f & 31) * 4;
            float4* pb = (float4*)&Bs[buf][kr][nq];
            *pb = make_float4(rb[p*4+0], rb[p*4+1], rb[p*4+2], rb[p*4+3]);
        }
    };

    loadTile(0);
    storeTile(0);
    __syncthreads();

    int buf = 0;
    for (int kt = 0; kt < K; kt += TBK) {
        int next = kt + TBK;
        bool more = next < K;
        if (more) loadTile(next);

#pragma unroll
        for (int kk = 0; kk < TBK; kk += 8) {
            uint32_t ahi[16], alo[16], bhi[8], blo[8];
#pragma unroll
            for (int mt = 0; mt < 4; mt++) {
                int mb = wm * 64 + mt * 16 + lm;
                split_tf32(As[buf][mb    ][kk + lk    ], ahi[mt*4+0], alo[mt*4+0]);
                split_tf32(As[buf][mb + 8][kk + lk    ], ahi[mt*4+1], alo[mt*4+1]);
                split_tf32(As[buf][mb    ][kk + lk + 4], ahi[mt*4+2], alo[mt*4+2]);
                split_tf32(As[buf][mb + 8][kk + lk + 4], ahi[mt*4+3], alo[mt*4+3]);
            }
#pragma unroll
            for (int nt = 0; nt < 4; nt++) {
                int nb = wn * 32 + nt * 8 + lm;
                split_tf32(Bs[buf][kk + lk    ][nb], bhi[nt*2+0], blo[nt*2+0]);
                split_tf32(Bs[buf][kk + lk + 4][nb], bhi[nt*2+1], blo[nt*2+1]);
            }
#pragma unroll
            for (int mt = 0; mt < 4; mt++)
#pragma unroll
                for (int nt = 0; nt < 4; nt++) {
                    float* d = acc[mt*4+nt];
                    mma_tf32(d, &ahi[mt*4], &bhi[nt*2]);
                    mma_tf32(d, &ahi[mt*4], &blo[nt*2]);
                    mma_tf32(d, &alo[mt*4], &bhi[nt*2]);
                }
        }
        if (more) {
            storeTile(buf ^ 1);
            __syncthreads();
            buf ^= 1;
        }
    }

    // ---- epilogue ----
#pragma unroll
    for (int mt = 0; mt < 4; mt++) {
#pragma unroll
        for (int nt = 0; nt < 4; nt++) {
            float* d = acc[mt*4+nt];
            int gm0 = m0 + wm * 64 + mt * 16 + lm;
            int gn0 = n0 + wn * 32 + nt * 8 + 2 * lk;
#pragma unroll
            for (int half = 0; half < 2; half++) {
                int gm = gm0 + half * 8;
                if (gm >= M) continue;
                float v0 = d[half*2+0], v1 = d[half*2+1];
                size_t idx = (size_t)gm * Nc + gn0;
                if (mode == 2) {
                    if (gn0 < Nc)     Cm[idx]     += 0.25f * v0;
                    if (gn0 + 1 < Nc) Cm[idx + 1] += 0.25f * v1;
                } else {
                    if (bias) { v0 += bias[gn0]; v1 += (gn0+1 < Nc) ? bias[gn0+1] : 0.f; }
                    if (mode == 1) {
                        v0 = (v0 > 0.f) ? v0 : 0.01f * v0;
                        v1 = (v1 > 0.f) ? v1 : 0.01f * v1;
                    }
                    if (gn0 + 1 < Nc) {
                        *(float2*)&Cm[idx] = make_float2(v0, v1);
                    } else if (gn0 < Nc) {
                        Cm[idx] = v0;
                    }
                }
            }
        }
    }
}

// ---------------------------------------------------------------------------
// Weight concat: wcat[l][i][0:1024]=wq, [1024:2048]=wk, [2048:3072]=wv,
// [4096:4352]=wskip.  (columns 3072:4096 = wqe, filled by wqe_k)
// ---------------------------------------------------------------------------
__global__ void wcat_k(const float* __restrict__ wq, const float* __restrict__ wk,
                       const float* __restrict__ wv, const float* __restrict__ wsk,
                       float* __restrict__ wcat)
{
    int idx = blockIdx.x * blockDim.x + threadIdx.x;
    int total = 3 * ND * PS;
    if (idx >= total) return;
    int l = idx / (ND * PS);
    int r = (idx / PS) % ND;
    int c = idx % PS;
    float v;
    if (c < 1024)       v = wq [(size_t)l * ND * HC + (size_t)r * HC + c];
    else if (c < 2048)  v = wk [(size_t)l * ND * HC + (size_t)r * HC + (c - 1024)];
    else if (c < 3072)  v = wv [(size_t)l * ND * HC + (size_t)r * HC + (c - 2048)];
    else if (c < 4096)  return;  // wqe slot, filled separately
    else                v = wsk[(size_t)l * ND * ND + (size_t)r * ND + (c - 4096)];
    wcat[idx] = v;
}

// ---------------------------------------------------------------------------
// Wqe precompute (fp32-exact FFMA; small): per (l,h):
//   Wqe_lh[i][d] = sum_c wq[l][i,hC+c] * we[l][d,hC+c]
// Written into wcat columns 3072 + h*256 + d (ldc = PS). grid (2,2,12).
// ---------------------------------------------------------------------------
#define QBM 128
#define QBN 128
#define QBK 8

__global__ __launch_bounds__(256)
void wqe_k(const float* __restrict__ wq, const float* __restrict__ we,
           float* __restrict__ wcat)
{
    __shared__ float As[QBK][QBM];
    __shared__ float Bs[QBK][QBN];

    int z = blockIdx.z;
    int l = z >> 2, h = z & 3;
    const float* A = wq + (size_t)l * ND * HC + h * NC;
    const float* B = we + (size_t)l * ND * HC + h * NC;
    float* C = wcat + (size_t)l * ND * PS + 3072 + h * NC;

    int tid = threadIdx.x;
    int m0 = blockIdx.y * QBM;
    int n0 = blockIdx.x * QBN;

    int arow = tid >> 1;
    int acol = (tid & 1) * 4;
    int mi = (tid >> 4) * 8;
    int ni = (tid & 15) * 8;

    float acc[8][8];
#pragma unroll
    for (int i = 0; i < 8; i++)
#pragma unroll
        for (int j = 0; j < 8; j++) acc[i][j] = 0.f;

    for (int kt = 0; kt < ND; kt += QBK) {
#pragma unroll
        for (int j = 0; j < 4; j++)
            As[acol + j][arow] = A[(size_t)(m0 + arow) * HC + kt + acol + j];
#pragma unroll
        for (int j = 0; j < 4; j++)
            Bs[acol + j][arow] = B[(size_t)(n0 + arow) * HC + kt + acol + j];
        __syncthreads();
#pragma unroll
        for (int k = 0; k < QBK; k++) {
            float a[8], b[8];
            float4 a0 = *(const float4*)&As[k][mi];
            float4 a1 = *(const float4*)&As[k][mi + 4];
            float4 b0 = *(const float4*)&Bs[k][ni];
            float4 b1 = *(const float4*)&Bs[k][ni + 4];
            a[0]=a0.x; a[1]=a0.y; a[2]=a0.z; a[3]=a0.w;
            a[4]=a1.x; a[5]=a1.y; a[6]=a1.z; a[7]=a1.w;
            b[0]=b0.x; b[1]=b0.y; b[2]=b0.z; b[3]=b0.w;
            b[4]=b1.x; b[5]=b1.y; b[6]=b1.z; b[7]=b1.w;
#pragma unroll
            for (int i = 0; i < 8; i++)
#pragma unroll
                for (int j = 0; j < 8; j++)
                    acc[i][j] += a[i] * b[j];
        }
        __syncthreads();
    }
#pragma unroll
    for (int i = 0; i < 8; i++)
#pragma unroll
        for (int j = 0; j < 8; j++)
            C[(size_t)(m0 + mi + i) * PS + n0 + ni + j] = acc[i][j];
}

// We_stack[l][h*256+d][c] = we[l][d][h*256+c]
__global__ void westack_k(const float* __restrict__ we, float* __restrict__ wes) {
    int idx = blockIdx.x * blockDim.x + threadIdx.x;
    if (idx >= 3 * HC * ND) return;
    int l = idx / (HC * ND);
    int r = (idx / ND) % HC;
    int c = idx % ND;
    int h = r >> 8, d = r & 255;
    wes[idx] = we[(size_t)l * ND * HC + (size_t)d * HC + h * NC + c];
}

// ---------------------------------------------------------------------------
// Node embedding gather
// ---------------------------------------------------------------------------
__global__ void embed_k(const int* __restrict__ ids,
                        const float* __restrict__ emb,
                        float* __restrict__ x)
{
    int idx = blockIdx.x * blockDim.x + threadIdx.x;
    if (idx >= NN * ND) return;
    int n = idx >> 8, c = idx & 255;
    x[idx] = emb[ids[n] * ND + c];
}

// ---------------------------------------------------------------------------
// CSR-by-target build
// ---------------------------------------------------------------------------
__global__ void csr_count_k(const int* __restrict__ ei, int* __restrict__ cnt) {
    int e = blockIdx.x * blockDim.x + threadIdx.x;
    if (e < NE) atomicAdd(&cnt[ei[NE + e]], 1);
}

__global__ __launch_bounds__(1024)
void scan_k(const int* __restrict__ cnt, int* __restrict__ off, int n) {
    __shared__ int sums[1024];
    int per = (n + 1023) / 1024;
    int start = threadIdx.x * per;
    int local = 0;
    for (int i = 0; i < per; i++) {
        int idx = start + i;
        if (idx < n) local += cnt[idx];
    }
    sums[threadIdx.x] = local;
    __syncthreads();
    for (int d = 1; d < 1024; d <<= 1) {
        int v = (threadIdx.x >= (unsigned)d) ? sums[threadIdx.x - d] : 0;
        __syncthreads();
        sums[threadIdx.x] += v;
        __syncthreads();
    }
    int base = (threadIdx.x == 0) ? 0 : sums[threadIdx.x - 1];
    int run = base;
    for (int i = 0; i < per; i++) {
        int idx = start + i;
        if (idx < n) { off[idx] = run; run += cnt[idx]; }
    }
    if (threadIdx.x == 1023) off[n] = sums[1023];
}

__global__ void csr_fill_k(const int* __restrict__ ei, int* __restrict__ cur,
                           int* __restrict__ csr) {
    int e = blockIdx.x * blockDim.x + threadIdx.x;
    if (e < NE) {
        int t = ei[NE + e];
        int p = atomicAdd(&cur[t], 1);
        csr[p] = e;
    }
}

// ---------------------------------------------------------------------------
// alpha[e,h] = (1/16)*( q[tgt,h]·k[src,h] + ea[e]·qe[tgt,h] )
// ---------------------------------------------------------------------------
__global__ __launch_bounds__(256)
void alpha_k(const int* __restrict__ ei,
             const float* __restrict__ proj,
             const float* __restrict__ ea,
             float* __restrict__ al)
{
    int wid = (blockIdx.x * blockDim.x + threadIdx.x) >> 5;
    int lane = threadIdx.x & 31;
    if (wid >= NE) return;
    int e = wid;
    int src = ei[e], tgt = ei[NE + e];
    const float* qr  = proj + (size_t)tgt * PS;
    const float* kr  = proj + (size_t)src * PS + 1024;
    const float* qer = proj + (size_t)tgt * PS + 3072;
    const float* ear = ea + (size_t)e * ND;
    float acc[4] = {0.f, 0.f, 0.f, 0.f};
    for (int c = lane; c < NC; c += 32) {
        float eav = ear[c];
#pragma unroll
        for (int h = 0; h < 4; h++)
            acc[h] += qr[h * NC + c] * kr[h * NC + c] + qer[h * NC + c] * eav;
    }
#pragma unroll
    for (int o = 16; o; o >>= 1)
#pragma unroll
        for (int h = 0; h < 4; h++)
            acc[h] += __shfl_xor_sync(0xffffffffu, acc[h], o);
    if (lane == 0) {
#pragma unroll
        for (int h = 0; h < 4; h++)
            al[e * NH + h] = acc[h] * 0.0625f;
    }
}

// ---------------------------------------------------------------------------
// Segment softmax: one warp per (node, head); alpha -> a in place
// ---------------------------------------------------------------------------
__global__ void softmax_k(const int* __restrict__ off,
                          const int* __restrict__ csr,
                          float* __restrict__ al)
{
    int wid = (blockIdx.x * blockDim.x + threadIdx.x) >> 5;
    int lane = threadIdx.x & 31;
    if (wid >= NN * NH) return;
    int n = wid >> 2, h = wid & 3;
    int s0 = off[n], s1 = off[n + 1];
    if (s0 == s1) return;
    float m = -INFINITY;
    for (int i = s0 + lane; i < s1; i += 32)
        m = fmaxf(m, al[csr[i] * NH + h]);
#pragma unroll
    for (int o = 16; o; o >>= 1) m = fmaxf(m, __shfl_xor_sync(0xffffffffu, m, o));
    float sum = 0.f;
    for (int i = s0 + lane; i < s1; i += 32) {
        int idx = csr[i] * NH + h;
        float ex = expf(al[idx] - m);
        al[idx] = ex;
        sum += ex;
    }
#pragma unroll
    for (int o = 16; o; o >>= 1) sum += __shfl_xor_sync(0xffffffffu, sum, o);
    float inv = 1.f / (sum + 1e-16f);
    for (int i = s0 + lane; i < s1; i += 32)
        al[csr[i] * NH + h] *= inv;
}

// ---------------------------------------------------------------------------
// Aggregation (one block per node, 256 threads = channel c)
// ---------------------------------------------------------------------------
__global__ __launch_bounds__(256)
void agg_k(const int* __restrict__ ei, const int* __restrict__ off,
           const int* __restrict__ csr, const float* __restrict__ al,
           const float* __restrict__ proj, const float* __restrict__ ea,
           float* __restrict__ aggea, float* __restrict__ xout)
{
    int n = blockIdx.x, c = threadIdx.x;
    int s0 = off[n], s1 = off[n + 1];
    float sv = 0.f;
    float ae[4] = {0.f, 0.f, 0.f, 0.f};
    for (int i = s0; i < s1; i++) {
        int e = csr[i];
        int src = ei[e];
        float a0 = al[e * NH + 0];
        float a1 = al[e * NH + 1];
        float a2 = al[e * NH + 2];
        float a3 = al[e * NH + 3];
        const float* vr = proj + (size_t)src * PS + 2048;
        sv += a0 * vr[c] + a1 * vr[NC + c] + a2 * vr[2 * NC + c] + a3 * vr[3 * NC + c];
        float eav = ea[(size_t)e * ND + c];
        ae[0] += a0 * eav; ae[1] += a1 * eav; ae[2] += a2 * eav; ae[3] += a3 * eav;
    }
    xout[(size_t)n * ND + c] = 0.25f * sv + proj[(size_t)n * PS + 4096 + c];
    float* ar = aggea + (size_t)n * HC;
    ar[c] = ae[0]; ar[NC + c] = ae[1]; ar[2 * NC + c] = ae[2]; ar[3 * NC + c] = ae[3];
}

// ---------------------------------------------------------------------------
// Graph pooling (sum / max / count) with atomics
// ---------------------------------------------------------------------------
__global__ __launch_bounds__(256)
void pool_k(const int* __restrict__ batch, const float* __restrict__ x,
            float* __restrict__ sum, unsigned* __restrict__ mx,
            int* __restrict__ bcnt)
{
    int n = blockIdx.x, c = threadIdx.x;
    int b = batch[n];
    float v = x[(size_t)n * ND + c];
    atomicAdd(&sum[b * ND + c], v);
    atomicMax(&mx[b * ND + c], fenc(v));
    if (c == 0) atomicAdd(&bcnt[b], 1);
}

__global__ __launch_bounds__(256)
void feat_k(const float* __restrict__ sum, const unsigned* __restrict__ mx,
            const int* __restrict__ bcnt, const float* __restrict__ en,
            float* __restrict__ feat)
{
    int b = blockIdx.x, c = threadIdx.x;
    float cnt = (float)bcnt[b];
    float s = sum[b * ND + c];
    feat[b * 896 + c]        = s / cnt;
    feat[b * 896 + 256 + c]  = fdec(mx[b * ND + c]);
    feat[b * 896 + 512 + c]  = s;
    if (c < 128) feat[b * 896 + 768 + c] = en[b * 128 + c];
}

// ---------------------------------------------------------------------------
// Host orchestration
// ---------------------------------------------------------------------------
static inline void run_gemm(const float* A, const float* B, const float* bias,
                            float* C, int M, int K, int Nc, int mode)
{
    dim3 grid((Nc + TBN - 1) / TBN, (M + TBM - 1) / TBM);
    sgemm<<<grid, 256>>>(A, B, bias, C, M, K, Nc, mode);
}

extern "C" void kernel_launch(void* const* d_in, const int* in_sizes, int n_in,
                              void* d_out, int out_size)
{
    const int*   x_ids   = (const int*)  d_in[0];
    const int*   ei      = (const int*)  d_in[1];
    const int*   batch   = (const int*)  d_in[2];
    const float* eattr   = (const float*)d_in[3];
    const float* energies= (const float*)d_in[4];
    const float* nemb    = (const float*)d_in[5];
    const float* ew1     = (const float*)d_in[6];
    const float* eb1     = (const float*)d_in[7];
    const float* ew2     = (const float*)d_in[8];
    const float* eb2     = (const float*)d_in[9];
    const float* wq      = (const float*)d_in[10];
    const float* wk      = (const float*)d_in[11];
    const float* wv      = (const float*)d_in[12];
    const float* we      = (const float*)d_in[13];
    const float* wsk     = (const float*)d_in[14];
    const float* fce_w1  = (const float*)d_in[15];
    const float* fce_b1  = (const float*)d_in[16];
    const float* fce_w2  = (const float*)d_in[17];
    const float* fce_b2  = (const float*)d_in[18];
    const float* fc_w1   = (const float*)d_in[19];
    const float* fc_b1   = (const float*)d_in[20];
    const float* fc_w2   = (const float*)d_in[21];
    const float* fc_b2   = (const float*)d_in[22];
    float* out = (float*)d_out;
    (void)in_sizes; (void)n_in; (void)out_size;

    float *px, *px2, *pproj, *pea, *ph1, *pal, *paggea, *pwcat, *pwes;
    float *psum, *pen1, *pen, *pfeat, *pfc1;
    int *pcnt, *poff, *pcur, *pcsr, *pbcnt;
    unsigned* pmx;
    cudaGetSymbolAddress((void**)&px,    g_x);
    cudaGetSymbolAddress((void**)&px2,   g_x2);
    cudaGetSymbolAddress((void**)&pproj, g_proj);
    cudaGetSymbolAddress((void**)&pea,   g_ea);
    cudaGetSymbolAddress((void**)&ph1,   g_h1);
    cudaGetSymbolAddress((void**)&pal,   g_al);
    cudaGetSymbolAddress((void**)&paggea,g_aggea);
    cudaGetSymbolAddress((void**)&pwcat, g_wcat);
    cudaGetSymbolAddress((void**)&pwes,  g_wes);
    cudaGetSymbolAddress((void**)&pcnt,  g_cnt);
    cudaGetSymbolAddress((void**)&poff,  g_off);
    cudaGetSymbolAddress((void**)&pcur,  g_cur);
    cudaGetSymbolAddress((void**)&pcsr,  g_csr);
    cudaGetSymbolAddress((void**)&psum,  g_sum);
    cudaGetSymbolAddress((void**)&pmx,   g_mx);
    cudaGetSymbolAddress((void**)&pbcnt, g_bcnt);
    cudaGetSymbolAddress((void**)&pen1,  g_en1);
    cudaGetSymbolAddress((void**)&pen,   g_en);
    cudaGetSymbolAddress((void**)&pfeat, g_feat);
    cudaGetSymbolAddress((void**)&pfc1,  g_fc1);

    // --- prep, then big projection GEMM early for ncu ---
    embed_k<<<(NN * ND + 255) / 256, 256>>>(x_ids, nemb, px);
    wcat_k<<<(3 * ND * PS + 255) / 256, 256>>>(wq, wk, wv, wsk, pwcat);
    {
        dim3 g(1, 1, 12);
        wqe_k<<<dim3(2, 2, 12), 256>>>(wq, we, pwcat);
        (void)g;
    }
    westack_k<<<(3 * HC * ND + 255) / 256, 256>>>(we, pwes);
    run_gemm(eattr, ew1, eb1, ph1, NE, 14, 128, 1);
    run_gemm(px, pwcat, nullptr, pproj, NN, ND, PS, 0);     // layer 0 projection
    run_gemm(ph1, ew2, eb2, pea, NE, 128, ND, 0);

    // --- CSR by target ---
    fill_u32<<<(NN + 255) / 256, 256>>>((unsigned*)pcnt, 0u, NN);
    csr_count_k<<<(NE + 255) / 256, 256>>>(ei, pcnt);
    scan_k<<<1, 1024>>>(pcnt, poff, NN);
    copy_i32<<<(NN + 255) / 256, 256>>>(pcur, poff, NN);
    csr_fill_k<<<(NE + 255) / 256, 256>>>(ei, pcur, pcsr);

    // --- 3 transformer layers ---
    float* xin = px;
    float* xout = px2;
    for (int l = 0; l < 3; l++) {
        const float* wcatl = pwcat + (size_t)l * ND * PS;
        const float* wesl  = pwes  + (size_t)l * HC * ND;

        if (l > 0)
            run_gemm(xin, wcatl, nullptr, pproj, NN, ND, PS, 0);

        alpha_k<<<(NE + 7) / 8, 256>>>(ei, pproj, pea, pal);
        softmax_k<<<(NN * NH + 7) / 8, 256>>>(poff, pcsr, pal);
        agg_k<<<NN, 256>>>(ei, poff, pcsr, pal, pproj, pea, paggea, xout);
        run_gemm(paggea, wesl, nullptr, xout, NN, HC, ND, 2);

        float* t = xin; xin = xout; xout = t;
    }

    // --- pooling ---
    fill_u32<<<(NB * ND + 255) / 256, 256>>>((unsigned*)psum, 0u, NB * ND);
    fill_u32<<<(NB * ND + 255) / 256, 256>>>(pmx, 0u, NB * ND);
    fill_u32<<<(NB + 255) / 256, 256>>>((unsigned*)pbcnt, 0u, NB);
    pool_k<<<NN, 256>>>(batch, xin, psum, pmx, pbcnt);

    // --- energy MLP ---
    run_gemm(energies, fce_w1, fce_b1, pen1, NB, 201, 256, 1);
    run_gemm(pen1, fce_w2, fce_b2, pen, NB, 256, 128, 0);

    // --- feature concat + head ---
    feat_k<<<NB, 256>>>(psum, pmx, pbcnt, pen, pfeat);
    run_gemm(pfeat, fc_w1, fc_b1, pfc1, NB, 896, 1024, 1);
    run_gemm(pfc1, fc_w2, fc_b2, out, NB, 1024, 804, 0);
}